// round 7
// baseline (speedup 1.0000x reference)
#include <cuda_runtime.h>
#include <stdint.h>
#include <math.h>

// ---------------------------------------------------------------------------
// out[b,o] = min_i ( x[b,i] + mask[o,i] ),  B=IN=OUT=512,  x in [0,1)
// mask in {0,1}  =>  out[b,o] = min over SELECTED i of x[b,i]  (sparse min).
// Selection = JAX threefry bernoulli (partitionable variant, validated R2-R6).
// ---------------------------------------------------------------------------

#define B_DIM   512
#define IN_DIM  512
#define OUT_DIM 512
#define OW      (OUT_DIM / 32)      // 16 o-words per i-row (transposed layout)

// transposed selection bitmask: bit o of g_selT[i*16 + (o>>5)]
__device__ uint32_t g_selT[IN_DIM * OW];
__device__ uint2    g_top[B_DIM * 64];   // (idx, exact valbits), sorted per b-row

// ---------------- Threefry-2x32 (constexpr) --------------------------------
struct TF2 { uint32_t a, b; };

__host__ __device__ constexpr uint32_t rotl32(uint32_t v, int r) {
    return (v << r) | (v >> (32 - r));
}

__host__ __device__ constexpr TF2 tf2x32(uint32_t k0, uint32_t k1,
                                         uint32_t x0, uint32_t x1) {
    uint32_t k2 = k0 ^ k1 ^ 0x1BD11BDAu;
    x0 += k0; x1 += k1;
    x0 += x1; x1 = rotl32(x1, 13) ^ x0;
    x0 += x1; x1 = rotl32(x1, 15) ^ x0;
    x0 += x1; x1 = rotl32(x1, 26) ^ x0;
    x0 += x1; x1 = rotl32(x1,  6) ^ x0;
    x0 += k1; x1 += k2 + 1u;
    x0 += x1; x1 = rotl32(x1, 17) ^ x0;
    x0 += x1; x1 = rotl32(x1, 29) ^ x0;
    x0 += x1; x1 = rotl32(x1, 16) ^ x0;
    x0 += x1; x1 = rotl32(x1, 24) ^ x0;
    x0 += k2; x1 += k0 + 2u;
    x0 += x1; x1 = rotl32(x1, 13) ^ x0;
    x0 += x1; x1 = rotl32(x1, 15) ^ x0;
    x0 += x1; x1 = rotl32(x1, 26) ^ x0;
    x0 += x1; x1 = rotl32(x1,  6) ^ x0;
    x0 += k0; x1 += k1 + 3u;
    x0 += x1; x1 = rotl32(x1, 17) ^ x0;
    x0 += x1; x1 = rotl32(x1, 29) ^ x0;
    x0 += x1; x1 = rotl32(x1, 16) ^ x0;
    x0 += x1; x1 = rotl32(x1, 24) ^ x0;
    x0 += k1; x1 += k2 + 4u;
    x0 += x1; x1 = rotl32(x1, 13) ^ x0;
    x0 += x1; x1 = rotl32(x1, 15) ^ x0;
    x0 += x1; x1 = rotl32(x1, 26) ^ x0;
    x0 += x1; x1 = rotl32(x1,  6) ^ x0;
    x0 += k2; x1 += k0 + 5u;
    return TF2{x0, x1};
}

constexpr TF2 KB = tf2x32(0u, 42u, 0u, 0u);   // k_bern (foldlike split of key 42)

// ---------------- bernoulli decision (validated) -----------------------------
__device__ __forceinline__ bool edge_selected(const float2 w, uint32_t n) {
    TF2 r = tf2x32(KB.a, KB.b, 0u, n);
    uint32_t bits = r.a ^ r.b;
    float u = __uint_as_float((bits >> 9) | 0x3F800000u) - 1.0f;
    float t = u * (1.0f + __expf(w.x - w.y));
    if (t < 1.0f - 1e-5f) return true;
    if (t > 1.0f + 1e-5f) return false;
    double e = exp((double)w.x - (double)w.y);       // boundary: exact fp64
    return ((double)u) * (1.0 + e) < 1.0;
}

// ---------------- bitonic helpers (2 elems/thread: e0=2t, e1=2t+1) ----------
#define BSWAP(A, PA, KEEPMIN) ((KEEPMIN) ? umin((A),(PA)) : umax((A),(PA)))

#define STAGE_J1(K) {                                                         \
    bool dir = (((2*t) & (K)) == 0);                                          \
    uint32_t lo = umin(a, b), hi = umax(a, b);                                \
    a = dir ? lo : hi; b = dir ? hi : lo; }

#define STAGE_SHFL(J, K) {                                                    \
    uint32_t pa = __shfl_xor_sync(0xFFFFFFFFu, a, (J) >> 1);                  \
    uint32_t pb = __shfl_xor_sync(0xFFFFFFFFu, b, (J) >> 1);                  \
    bool dir = (((2*t) & (K)) == 0);                                          \
    bool lower = ((t & ((J) >> 1)) == 0);                                     \
    bool km = (dir == lower);                                                 \
    a = BSWAP(a, pa, km); b = BSWAP(b, pb, km); }

#define STAGE_SMEM(J, K) {                                                    \
    __syncthreads();                                                          \
    sk[2*t] = a; sk[2*t+1] = b;                                               \
    __syncthreads();                                                          \
    uint32_t pa = sk[(2*t) ^ (J)];                                            \
    uint32_t pb = sk[(2*t+1) ^ (J)];                                          \
    bool dir = (((2*t) & (K)) == 0);                                          \
    bool lower = (((2*t) & (J)) == 0);                                        \
    bool km = (dir == lower);                                                 \
    a = BSWAP(a, pa, km); b = BSWAP(b, pb, km); }

#define TAIL32(K) STAGE_SHFL(32,K) STAGE_SHFL(16,K) STAGE_SHFL(8,K) \
                  STAGE_SHFL(4,K)  STAGE_SHFL(2,K)  STAGE_J1(K)

// ---------------- 1) combined mask + sort (block-divergent grid) ------------
// blocks [0,512): sort b-row.  blocks [512,768): mask 32o x 32i tile, ILP=4.
__global__ __launch_bounds__(256) void prep_kernel(
    const float* __restrict__ x, const float* __restrict__ pw) {
    __shared__ uint32_t sk[512];
    __shared__ float s_xv[512];
    const int t = threadIdx.x;

    if (blockIdx.x >= 512) {
        // ---- mask tile: lane = o (ballot dim), warp+k = i ; 4 chains/thread
        const uint32_t m  = blockIdx.x - 512;       // 0..255
        const uint32_t ob = (m & 15u) * 32u;        // o-block
        const uint32_t ib = (m >> 4) * 32u;         // i-block
        const uint32_t l  = t & 31u;
        const uint32_t w  = (uint32_t)t >> 5;
        const uint32_t o  = ob + l;
        const uint32_t ow = ob >> 5;

        uint32_t iidx[4];
        bool s[4];
#pragma unroll
        for (int k = 0; k < 4; ++k) {
            iidx[k] = ib + w + 8u * k;
            uint32_t n = o * 512u + iidx[k];
            float2 wt = reinterpret_cast<const float2*>(pw)[n];
            s[k] = edge_selected(wt, n);
        }
#pragma unroll
        for (int k = 0; k < 4; ++k) {
            uint32_t word = __ballot_sync(0xFFFFFFFFu, s[k]);
            if (l == 0) g_selT[iidx[k] * OW + ow] = word;
        }
        return;
    }

    // ---- sort half: bitonic on 512 keys, 2 per thread in registers
    const int row = blockIdx.x;
    float2 xv = reinterpret_cast<const float2*>(x + row * IN_DIM)[t];
    s_xv[2*t]   = xv.x;                        // exact values for final emit
    s_xv[2*t+1] = xv.y;
    // key = (valbits>>7)<<9 | idx  (monotone in value, 128-ulp ties)
    uint32_t a = ((__float_as_uint(xv.x) >> 7) << 9) | (uint32_t)(2*t);
    uint32_t b = ((__float_as_uint(xv.y) >> 7) << 9) | (uint32_t)(2*t+1);

    // k = 2..64 : registers + shfl only
    STAGE_J1(2)
    STAGE_SHFL(2,4)  STAGE_J1(4)
    STAGE_SHFL(4,8)  STAGE_SHFL(2,8)  STAGE_J1(8)
    STAGE_SHFL(8,16) STAGE_SHFL(4,16) STAGE_SHFL(2,16) STAGE_J1(16)
    STAGE_SHFL(16,32) STAGE_SHFL(8,32) STAGE_SHFL(4,32) STAGE_SHFL(2,32) STAGE_J1(32)
    STAGE_SHFL(32,64) STAGE_SHFL(16,64) STAGE_SHFL(8,64) STAGE_SHFL(4,64)
    STAGE_SHFL(2,64)  STAGE_J1(64)
    // k = 128 / 256 / 512 (cross-warp via smem; barriers also fence s_xv)
    STAGE_SMEM(64,128)  TAIL32(128)
    STAGE_SMEM(128,256) STAGE_SMEM(64,256) TAIL32(256)
    STAGE_SMEM(256,512) STAGE_SMEM(128,512) STAGE_SMEM(64,512) TAIL32(512)

    if (t < 32) {                      // threads 0..31 hold sorted elems 0..63
        uint32_t ia = a & 511u, ib2 = b & 511u;
        g_top[row * 64 + 2*t]     = make_uint2(ia, __float_as_uint(s_xv[ia]));
        g_top[row * 64 + 2*t + 1] = make_uint2(ib2, __float_as_uint(s_xv[ib2]));
    }
}

// ---------------- 2) gather: first selected candidate, branch-free chunks ---
// One CTA per b-row; warp handles 32 consecutive o's -> o>>5 warp-uniform,
// so each candidate costs ONE broadcast LDG for the whole warp.
__global__ __launch_bounds__(256) void gather_kernel(
    const float* __restrict__ x, float* __restrict__ out) {
    __shared__ uint32_t s_idx16[64];   // idx*16 (pre-scaled row offset)
    __shared__ float    s_val[64];

    const int b = blockIdx.x;
    const int t = threadIdx.x;

    if (t < 64) {
        uint2 kv = g_top[b * 64 + t];
        s_idx16[t] = kv.x * OW;
        s_val[t]   = __uint_as_float(kv.y);
    }
    __syncthreads();

#pragma unroll 1
    for (int half = 0; half < 2; ++half) {
        const int o = half * 256 + t;
        const uint32_t ow   = (uint32_t)o >> 5;    // warp-uniform
        const uint32_t obit = (uint32_t)o & 31u;

        float res;
        bool found = false;
#pragma unroll 1
        for (int c = 0; c < 4 && !found; ++c) {    // expected ~1.07 chunks
            uint32_t m = 0;
#pragma unroll
            for (int jj = 0; jj < 16; ++jj) {      // 16 independent bcast LDGs
                uint32_t wsel = g_selT[s_idx16[c * 16 + jj] + ow];
                m |= ((wsel >> obit) & 1u) << jj;
            }
            if (m) { res = s_val[c * 16 + (__ffs(m) - 1)]; found = true; }
        }
        if (!found) {                              // P ~ 2e-9: exact dense scan
            float best = INFINITY, ball = INFINITY;
            const float* xr = x + b * IN_DIM;
            for (int i = 0; i < IN_DIM; ++i) {
                float v = xr[i];
                ball = fminf(ball, v);
                if ((g_selT[i * OW + ow] >> obit) & 1u) best = fminf(best, v);
            }
            res = isinf(best) ? ball + 1.0f : best;
        }
        out[b * OUT_DIM + o] = res;
    }
}

// ---------------------------------------------------------------------------
extern "C" void kernel_launch(void* const* d_in, const int* in_sizes, int n_in,
                              void* d_out, int out_size) {
    const float* x  = (const float*)d_in[0];   // [512, 512]
    const float* pw = (const float*)d_in[1];   // [512, 512, 2]
    float* out      = (float*)d_out;           // [512, 512]

    prep_kernel<<<768, 256>>>(x, pw);
    gather_kernel<<<B_DIM, 256>>>(x, out);
}